// round 15
// baseline (speedup 1.0000x reference)
#include <cuda_runtime.h>
#include <cuda_bf16.h>
#include <math.h>
#include <stdint.h>

// ---------------- problem dims ----------------
#define Bn   256
#define Sn   256
#define Dn   512
#define Hn   8
#define Vn   1024
#define Ln   4
#define FFNn 128
#define Mn   (Bn*Sn)

// ---------------- scratch ----------------
__device__ float g_X  [33554432];
__device__ float g_QKV[134217728];   // Mn*2048 fused Q|K|V (also head H2)
__device__ float g_Y  [67108864];
__device__ float g_Yr [33554432];
__device__ __nv_bfloat16 g_Xnh[33554432];
__device__ __nv_bfloat16 g_Xnl[33554432];
__device__ __nv_bfloat16 g_GYh[67108864];
__device__ __nv_bfloat16 g_GYl[67108864];
__device__ __nv_bfloat16 g_F1h[8388608];
__device__ __nv_bfloat16 g_F1l[8388608];
__device__ __nv_bfloat16 g_whi[9437184];
__device__ __nv_bfloat16 g_wlo[9437184];
__device__ float g_sin[8192];
__device__ float g_cos[8192];
__device__ float g_scl[8192];
__device__ float g_lg2[8];

#define LSW    2228224
#define OFF_WQ 0
#define OFF_WK 262144
#define OFF_WV 524288
#define OFF_WG 1048576
#define OFF_WO 1572864
#define OFF_F1 2097152
#define OFF_F2 2162688
#define OFF_H1 8912896
#define OFF_H2 9175040

#define EPI_NONE          0
#define EPI_SILU_MUL      1
#define EPI_ADD_RES       2
#define EPI_BIAS_GELU     3
#define EPI_BIAS_ADD_RES  4
#define EPI_BIAS_WAVE     5
#define EPI_GN_SILU_MUL   6

// ---------------- PTX helpers ----------------
__device__ __forceinline__ uint32_t smem_u32(const void* p) {
    uint32_t a;
    asm("{ .reg .u64 t; cvta.to.shared.u64 t, %1; cvt.u32.u64 %0, t; }" : "=r"(a) : "l"(p));
    return a;
}
__device__ __forceinline__ void ldsm4(uint32_t& r0, uint32_t& r1, uint32_t& r2, uint32_t& r3,
                                      uint32_t addr) {
    asm volatile("ldmatrix.sync.aligned.m8n8.x4.shared.b16 {%0,%1,%2,%3}, [%4];"
                 : "=r"(r0), "=r"(r1), "=r"(r2), "=r"(r3) : "r"(addr));
}
__device__ __forceinline__ void ldsm4t(uint32_t& r0, uint32_t& r1, uint32_t& r2, uint32_t& r3,
                                       uint32_t addr) {
    asm volatile("ldmatrix.sync.aligned.m8n8.x4.trans.shared.b16 {%0,%1,%2,%3}, [%4];"
                 : "=r"(r0), "=r"(r1), "=r"(r2), "=r"(r3) : "r"(addr));
}
__device__ __forceinline__ void mma_bf16(float* c, const uint32_t* a, const uint32_t* b) {
    asm volatile(
        "mma.sync.aligned.m16n8k16.row.col.f32.bf16.bf16.f32 "
        "{%0,%1,%2,%3}, {%4,%5,%6,%7}, {%8,%9}, {%0,%1,%2,%3};"
        : "+f"(c[0]), "+f"(c[1]), "+f"(c[2]), "+f"(c[3])
        : "r"(a[0]), "r"(a[1]), "r"(a[2]), "r"(a[3]), "r"(b[0]), "r"(b[1]));
}
__device__ __forceinline__ void cpa16(uint32_t dst, const void* src) {
    asm volatile("cp.async.cg.shared.global [%0], [%1], 16;" :: "r"(dst), "l"(src));
}
__device__ __forceinline__ void cpa_commit() {
    asm volatile("cp.async.commit_group;" ::: "memory");
}
template<int NN> __device__ __forceinline__ void cpa_wait() {
    asm volatile("cp.async.wait_group %0;" :: "n"(NN) : "memory");
}
__device__ __forceinline__ uint32_t pack_bf16_hi2(float a, float b, uint32_t& lo) {
    __nv_bfloat16 h0 = __float2bfloat16(a);
    __nv_bfloat16 h1 = __float2bfloat16(b);
    __nv_bfloat16 l0 = __float2bfloat16(a - __bfloat162float(h0));
    __nv_bfloat16 l1 = __float2bfloat16(b - __bfloat162float(h1));
    lo = (uint32_t)__bfloat16_as_ushort(l0) | ((uint32_t)__bfloat16_as_ushort(l1) << 16);
    return (uint32_t)__bfloat16_as_ushort(h0) | ((uint32_t)__bfloat16_as_ushort(h1) << 16);
}

// ---------------- small kernels ----------------
__global__ void k_tables(float* __restrict__ st, float* __restrict__ ct,
                         float* __restrict__ sc, float* __restrict__ lg)
{
    int idx = blockIdx.x * blockDim.x + threadIdx.x;
    if (idx < Sn * 32) {
        int s = idx >> 5, i = idx & 31;
        float sv = (2.0f * (float)i + 0.4f * 64.0f) / (1.4f * 64.0f);
        sc[idx] = powf(sv, (float)s / 512.0f);
        float invf = powf(10000.0f, -(float)i / 32.0f);
        float ang = (float)s * invf;
        st[idx] = sinf(ang);
        ct[idx] = cosf(ang);
    }
    if (idx < Hn) {
        float l0 = logf(1.0f / 32.0f);
        float l1 = logf(1.0f / 512.0f);
        float lj = l0 + (float)idx * (l1 - l0) / 7.0f;
        float gamma = 1.0f - expf(lj);
        lg[idx] = log2f(gamma);
    }
}

// single consolidated weight-prep kernel: grid.y = weight type, grid.z = layer
__global__ void k_prepw_all(const float* __restrict__ WQ, const float* __restrict__ WK,
                            const float* __restrict__ WV, const float* __restrict__ WG,
                            const float* __restrict__ WO, const float* __restrict__ F1w,
                            const float* __restrict__ F2w, const float* __restrict__ H1w,
                            const float* __restrict__ H2w,
                            __nv_bfloat16* __restrict__ hi, __nv_bfloat16* __restrict__ lo)
{
    const int wtype = blockIdx.y;
    const int l = blockIdx.z;
    const float* src;
    int Nn, Kk, mode;
    long srcStride;
    size_t dof;
    switch (wtype) {
        case 0: src = WQ;  Nn = 512;  Kk = 512;  mode = 1; srcStride = 262144; dof = OFF_WQ + (size_t)l * LSW; break;
        case 1: src = WK;  Nn = 512;  Kk = 512;  mode = 1; srcStride = 262144; dof = OFF_WK + (size_t)l * LSW; break;
        case 2: src = WV;  Nn = 1024; Kk = 512;  mode = 2; srcStride = 524288; dof = OFF_WV + (size_t)l * LSW; break;
        case 3: src = WG;  Nn = 1024; Kk = 512;  mode = 0; srcStride = 524288; dof = OFF_WG + (size_t)l * LSW; break;
        case 4: src = WO;  Nn = 512;  Kk = 1024; mode = 0; srcStride = 524288; dof = OFF_WO + (size_t)l * LSW; break;
        case 5: src = F1w; Nn = 128;  Kk = 512;  mode = 0; srcStride = 65536;  dof = OFF_F1 + (size_t)l * LSW; break;
        case 6: src = F2w; Nn = 512;  Kk = 128;  mode = 0; srcStride = 65536;  dof = OFF_F2 + (size_t)l * LSW; break;
        case 7: if (l != 0) return;
                src = H1w; Nn = 512;  Kk = 512;  mode = 0; srcStride = 0;      dof = OFF_H1; break;
        default: if (l != 0) return;
                src = H2w; Nn = 512;  Kk = 512;  mode = 0; srcStride = 0;      dof = OFF_H2; break;
    }
    int idx = blockIdx.x * blockDim.x + threadIdx.x;
    if (idx >= Nn * Kk) return;
    const float* s = src + (size_t)l * srcStride;
    int n = idx / Kk, k = idx % Kk;
    float v;
    if (mode == 0) v = s[(size_t)k * Nn + n];
    else if (mode == 1) { int h = n >> 6, e = n & 63;  v = s[((size_t)h * Kk + k) * 64 + e]; }
    else                { int h = n >> 7, vv = n & 127; v = s[((size_t)h * Kk + k) * 128 + vv]; }
    __nv_bfloat16 hv = __float2bfloat16(v);
    __nv_bfloat16 lv = __float2bfloat16(v - __bfloat162float(hv));
    hi[dof + idx] = hv;
    lo[dof + idx] = lv;
}

// fused embed + layer-0 layernorm (warp per token)
__global__ void k_embed_ln(const float* __restrict__ x, const float* __restrict__ t,
                           const float* __restrict__ eW, const float* __restrict__ eb,
                           float* __restrict__ X,
                           __nv_bfloat16* __restrict__ Ohi, __nv_bfloat16* __restrict__ Olo,
                           const float* __restrict__ w, const float* __restrict__ b)
{
    int gw   = (blockIdx.x * blockDim.x + threadIdx.x) >> 5;
    int lane = threadIdx.x & 31;
    if (gw >= Mn) return;
    float xv = x[gw], tv = t[gw];
    float4 v[4];
    float s = 0.f, ss = 0.f;
#pragma unroll
    for (int q = 0; q < 4; q++) {
        int d = q * 128 + lane * 4;
        float4 w0 = *(const float4*)(eW + d);
        float4 w1 = *(const float4*)(eW + Dn + d);
        float4 bb = *(const float4*)(eb + d);
        v[q].x = xv * w0.x + tv * w1.x + bb.x;
        v[q].y = xv * w0.y + tv * w1.y + bb.y;
        v[q].z = xv * w0.z + tv * w1.z + bb.z;
        v[q].w = xv * w0.w + tv * w1.w + bb.w;
        *(float4*)(X + (size_t)gw * 512 + d) = v[q];
        s  += v[q].x + v[q].y + v[q].z + v[q].w;
        ss += v[q].x * v[q].x + v[q].y * v[q].y + v[q].z * v[q].z + v[q].w * v[q].w;
    }
#pragma unroll
    for (int o = 16; o > 0; o >>= 1) {
        s  += __shfl_xor_sync(0xffffffffu, s,  o);
        ss += __shfl_xor_sync(0xffffffffu, ss, o);
    }
    float mu  = s * (1.0f / 512.0f);
    float var = ss * (1.0f / 512.0f) - mu * mu;
    float rs  = rsqrtf(var + 1e-5f);
#pragma unroll
    for (int q = 0; q < 4; q++) {
        int d = q * 128 + lane * 4;
        float4 wv = *(const float4*)(w + d);
        float4 bv = *(const float4*)(b + d);
        float o0 = (v[q].x - mu) * rs * wv.x + bv.x;
        float o1 = (v[q].y - mu) * rs * wv.y + bv.y;
        float o2 = (v[q].z - mu) * rs * wv.z + bv.z;
        float o3 = (v[q].w - mu) * rs * wv.w + bv.w;
        uint2 hu, lu;
        hu.x = pack_bf16_hi2(o0, o1, lu.x);
        hu.y = pack_bf16_hi2(o2, o3, lu.y);
        *(uint2*)(Ohi + (size_t)gw * 512 + d) = hu;
        *(uint2*)(Olo + (size_t)gw * 512 + d) = lu;
    }
}

__global__ void k_ln(const float* __restrict__ Xin, __nv_bfloat16* __restrict__ Ohi,
                     __nv_bfloat16* __restrict__ Olo,
                     const float* __restrict__ w, const float* __restrict__ b)
{
    int gw   = (blockIdx.x * blockDim.x + threadIdx.x) >> 5;
    int lane = threadIdx.x & 31;
    if (gw >= Mn) return;
    const float* row = Xin + (size_t)gw * 512;
    float4 v[4];
    float s = 0.f, ss = 0.f;
#pragma unroll
    for (int q = 0; q < 4; q++) {
        v[q] = *(const float4*)(row + q * 128 + lane * 4);
        s  += v[q].x + v[q].y + v[q].z + v[q].w;
        ss += v[q].x * v[q].x + v[q].y * v[q].y + v[q].z * v[q].z + v[q].w * v[q].w;
    }
#pragma unroll
    for (int o = 16; o > 0; o >>= 1) {
        s  += __shfl_xor_sync(0xffffffffu, s,  o);
        ss += __shfl_xor_sync(0xffffffffu, ss, o);
    }
    float mu  = s * (1.0f / 512.0f);
    float var = ss * (1.0f / 512.0f) - mu * mu;
    float rs  = rsqrtf(var + 1e-5f);
#pragma unroll
    for (int q = 0; q < 4; q++) {
        int d = q * 128 + lane * 4;
        float4 wv = *(const float4*)(w + d);
        float4 bv = *(const float4*)(b + d);
        float o0 = (v[q].x - mu) * rs * wv.x + bv.x;
        float o1 = (v[q].y - mu) * rs * wv.y + bv.y;
        float o2 = (v[q].z - mu) * rs * wv.z + bv.z;
        float o3 = (v[q].w - mu) * rs * wv.w + bv.w;
        uint2 hu, lu;
        hu.x = pack_bf16_hi2(o0, o1, lu.x);
        hu.y = pack_bf16_hi2(o2, o3, lu.y);
        *(uint2*)(Ohi + (size_t)gw * 512 + d) = hu;
        *(uint2*)(Olo + (size_t)gw * 512 + d) = lu;
    }
}

// ================= GEMM (R12 config) =================
#define STG   24576
#define GK_SMEM (4*STG)
#define GSTR 24
__global__ void __launch_bounds__(256, 2) k_gemm_s(
    const __nv_bfloat16* __restrict__ Ahi, const __nv_bfloat16* __restrict__ Alo,
    const __nv_bfloat16* __restrict__ Bhi, const __nv_bfloat16* __restrict__ Blo,
    float* __restrict__ Cf, __nv_bfloat16* __restrict__ Chi, __nv_bfloat16* __restrict__ Clo,
    const int M, const int N, const int K,
    const float* __restrict__ bias, const float* __restrict__ extra,
    const float* __restrict__ wptr, const int woff, const int epi)
{
    extern __shared__ char smc[];
    const uint32_t sb = smem_u32(smc);
    const int tid = threadIdx.x;
    const int lane = tid & 31;
    const int wid = tid >> 5;
    const int wm = wid & 3;
    const int wn = wid >> 2;
    const int m0 = blockIdx.y * 128;
    const int n0 = blockIdx.x * 128;

    float acc[16][4];
#pragma unroll
    for (int i = 0; i < 16; i++)
#pragma unroll
        for (int j = 0; j < 4; j++) acc[i][j] = 0.f;

    const int nch = K >> 4;
    const int row  = tid >> 1;
    const int hcol = (tid & 1) * 8;
    const uint32_t sdst = (uint32_t)((row * GSTR + hcol) * 2);
    const __nv_bfloat16* gA  = Ahi + (size_t)(m0 + row) * K + hcol;
    const __nv_bfloat16* gAl = Alo + (size_t)(m0 + row) * K + hcol;
    const __nv_bfloat16* gB  = Bhi + (size_t)(n0 + row) * K + hcol;
    const __nv_bfloat16* gBl = Blo + (size_t)(n0 + row) * K + hcol;

#define ISSUE(c) do {                                   \
        const uint32_t stb = sb + ((c) & 3) * STG;      \
        const int ko = (c) * 16;                        \
        cpa16(stb + sdst,          gA  + ko);           \
        cpa16(stb +  6144 + sdst,  gAl + ko);           \
        cpa16(stb + 12288 + sdst,  gB  + ko);           \
        cpa16(stb + 18432 + sdst,  gBl + ko);           \
    } while (0)

    ISSUE(0); cpa_commit();
    ISSUE(1); cpa_commit();
    ISSUE(2); cpa_commit();

    const int a_lo = (wm * 32 + (lane & 15)) * GSTR + (lane >> 4) * 8;
    const int b_lo = (wn * 64 + (lane & 15)) * GSTR + (lane >> 4) * 8;

    for (int c = 0; c < nch; c++) {
        cpa_wait<2>();
        __syncthreads();
        if (c + 3 < nch) ISSUE(c + 3);
        cpa_commit();

        const uint32_t st = (c & 3) * STG;
        const uint32_t abase = sb + st + a_lo * 2;
        const uint32_t bbase = sb + st + 12288 + b_lo * 2;

        uint32_t ah[2][4], al[2][4];
#pragma unroll
        for (int mt = 0; mt < 2; mt++)
            ldsm4(ah[mt][0], ah[mt][1], ah[mt][2], ah[mt][3], abase + mt * 16 * GSTR * 2);
#pragma unroll
        for (int mt = 0; mt < 2; mt++)
            ldsm4(al[mt][0], al[mt][1], al[mt][2], al[mt][3], abase + 6144 + mt * 16 * GSTR * 2);

#pragma unroll
        for (int nt2 = 0; nt2 < 4; nt2++) {
            uint32_t r0, r1, r2, r3, s0, s1, s2, s3;
            ldsm4(r0, r1, r2, r3, bbase + nt2 * 16 * GSTR * 2);
            ldsm4(s0, s1, s2, s3, bbase + 6144 + nt2 * 16 * GSTR * 2);
            uint32_t bh0[2] = {r0, r2}, bh1[2] = {r1, r3};
            uint32_t bl0[2] = {s0, s2}, bl1[2] = {s1, s3};
#pragma unroll
            for (int mt = 0; mt < 2; mt++) {
                float* a0 = acc[mt * 8 + 2 * nt2];
                float* a1 = acc[mt * 8 + 2 * nt2 + 1];
                mma_bf16(a0, ah[mt], bh0);
                mma_bf16(a1, ah[mt], bh1);
                mma_bf16(a0, al[mt], bh0);
                mma_bf16(a1, al[mt], bh1);
                mma_bf16(a0, ah[mt], bl0);
                mma_bf16(a1, ah[mt], bl1);
            }
        }
    }
    cpa_wait<0>();
    __syncthreads();

    float* ep = (float*)smc;
#pragma unroll
    for (int mt = 0; mt < 2; mt++)
#pragma unroll
        for (int nt = 0; nt < 8; nt++) {
            int r = wm * 32 + mt * 16 + (lane >> 2);
            int cc = wn * 64 + nt * 8 + (lane & 3) * 2;
            *(float2*)(ep + r * 132 + cc) = make_float2(acc[mt * 8 + nt][0], acc[mt * 8 + nt][1]);
            *(float2*)(ep + (r + 8) * 132 + cc) = make_float2(acc[mt * 8 + nt][2], acc[mt * 8 + nt][3]);
        }
    __syncthreads();

    float w0 = 0.f, w1 = 0.f;
    if (epi == EPI_BIAS_WAVE) { w0 = wptr[woff]; w1 = wptr[woff + 1]; }
#pragma unroll 1
    for (int i = 0; i < 16; i++) {
        int f = i * 256 + tid;
        int r = f >> 5;
        int c4 = (f & 31) * 4;
        float4 v = *(const float4*)(ep + r * 132 + c4);
        size_t base = (size_t)(m0 + r) * N + n0 + c4;
        if (epi == EPI_SILU_MUL) {
            float4 e = *(const float4*)(extra + base);
            v.x = v.x * e.x / (1.0f + expf(-v.x));
            v.y = v.y * e.y / (1.0f + expf(-v.y));
            v.z = v.z * e.z / (1.0f + expf(-v.z));
            v.w = v.w * e.w / (1.0f + expf(-v.w));
        } else if (epi == EPI_GN_SILU_MUL) {
            float4 e = *(const float4*)(extra + base);
            float s  = e.x + e.y + e.z + e.w;
            float ss = e.x * e.x + e.y * e.y + e.z * e.z + e.w * e.w;
#pragma unroll
            for (int o = 16; o > 0; o >>= 1) {
                s  += __shfl_xor_sync(0xffffffffu, s,  o);
                ss += __shfl_xor_sync(0xffffffffu, ss, o);
            }
            float mu  = s * (1.0f / 128.0f);
            float var = ss * (1.0f / 128.0f) - mu * mu;
            float rs  = rsqrtf(var + 1e-5f);
            float4 gwv = *(const float4*)(bias + n0 + c4);
            float4 gbv = *(const float4*)(wptr + n0 + c4);
            float n0v = (e.x - mu) * rs * gwv.x + gbv.x;
            float n1v = (e.y - mu) * rs * gwv.y + gbv.y;
            float n2v = (e.z - mu) * rs * gwv.z + gbv.z;
            float n3v = (e.w - mu) * rs * gwv.w + gbv.w;
            v.x = v.x * n0v / (1.0f + expf(-v.x));
            v.y = v.y * n1v / (1.0f + expf(-v.y));
            v.z = v.z * n2v / (1.0f + expf(-v.z));
            v.w = v.w * n3v / (1.0f + expf(-v.w));
        } else if (epi == EPI_ADD_RES) {
            float4 e = *(const float4*)(extra + base);
            v.x += e.x; v.y += e.y; v.z += e.z; v.w += e.w;
        } else if (epi == EPI_BIAS_GELU) {
            float4 bb = *(const float4*)(bias + n0 + c4);
            v.x += bb.x; v.y += bb.y; v.z += bb.z; v.w += bb.w;
            v.x = 0.5f * v.x * (1.0f + erff(v.x * 0.70710678118f));
            v.y = 0.5f * v.y * (1.0f + erff(v.y * 0.70710678118f));
            v.z = 0.5f * v.z * (1.0f + erff(v.z * 0.70710678118f));
            v.w = 0.5f * v.w * (1.0f + erff(v.w * 0.70710678118f));
        } else if (epi == EPI_BIAS_ADD_RES) {
            float4 bb = *(const float4*)(bias + n0 + c4);
            float4 e  = *(const float4*)(extra + base);
            v.x += bb.x + e.x; v.y += bb.y + e.y; v.z += bb.z + e.z; v.w += bb.w + e.w;
        } else if (epi == EPI_BIAS_WAVE) {
            float4 bb = *(const float4*)(bias + n0 + c4);
            v.x += bb.x; v.y += bb.y; v.z += bb.z; v.w += bb.w;
            v.x = w0 * sinf(v.x) + w1 * cosf(v.x);
            v.y = w0 * sinf(v.y) + w1 * cosf(v.y);
            v.z = w0 * sinf(v.z) + w1 * cosf(v.z);
            v.w = w0 * sinf(v.w) + w1 * cosf(v.w);
        }
        if (Cf) *(float4*)(Cf + base) = v;
        if (Chi) {
            uint2 hu, lu;
            hu.x = pack_bf16_hi2(v.x, v.y, lu.x);
            hu.y = pack_bf16_hi2(v.z, v.w, lu.y);
            *(uint2*)(Chi + base) = hu;
            *(uint2*)(Clo + base) = lu;
        }
    }
#undef ISSUE
}

// ================= HMMA split-bf16 retention attention (fused QKV input) =================
#define AT_SMEM 90112
#define AQ  0
#define AK  18432
#define AP  36864
#define AVH 55296
#define AVL 72704
__global__ void __launch_bounds__(256, 2) k_attn_mma(
    const float* __restrict__ QKV, float* __restrict__ Yp,
    const float* __restrict__ tsin, const float* __restrict__ tcos,
    const float* __restrict__ tscl, const float* __restrict__ lg2)
{
    extern __shared__ char smc[];
    const uint32_t sb = smem_u32(smc);
    const int st = blockIdx.x;
    const int bh = blockIdx.y;
    const int b = bh >> 3, h = bh & 7;
    const float lg = lg2[h];
    const int tid = threadIdx.x;
    const int lane = tid & 31;
    const int wid = tid >> 5;
    const int wm = wid & 3;
    const int wn = wid >> 2;
    const int s0 = st * 64;

#pragma unroll
    for (int i = 0; i < 4; i++) {
        int f = i * 256 + tid;
        int r = f >> 4;
        int e0 = (f & 15) * 4;
        float4 v = *(const float4*)(QKV + ((size_t)(b * Sn + s0 + r)) * 2048 + h * 64 + e0);
        int s = s0 + r;
        int i0 = e0 >> 1;
        float sc0 = tscl[s * 32 + i0],     sc1 = tscl[s * 32 + i0 + 1];
        float c0 = tcos[s * 32 + i0] * sc0, n0 = tsin[s * 32 + i0] * sc0;
        float c1 = tcos[s * 32 + i0 + 1] * sc1, n1 = tsin[s * 32 + i0 + 1] * sc1;
        float q0 = v.x * c0 - v.y * n0;
        float q1 = v.y * c0 + v.x * n0;
        float q2 = v.z * c1 - v.w * n1;
        float q3 = v.w * c1 + v.z * n1;
        uint2 hu, lu;
        hu.x = pack_bf16_hi2(q0, q1, lu.x);
        hu.y = pack_bf16_hi2(q2, q3, lu.y);
        uint32_t off = (uint32_t)(r * 144 + e0 * 2);
        *(uint2*)(smc + AQ + off)        = hu;
        *(uint2*)(smc + AQ + 9216 + off) = lu;
    }

    float yacc[8][4];
#pragma unroll
    for (int i = 0; i < 8; i++)
#pragma unroll
        for (int j = 0; j < 4; j++) yacc[i][j] = 0.f;

    for (int mt = 0; mt <= st; mt++) {
        const int m0 = mt * 64;
        __syncthreads();
#pragma unroll
        for (int i = 0; i < 4; i++) {
            int f = i * 256 + tid;
            int r = f >> 4;
            int e0 = (f & 15) * 4;
            float4 v = *(const float4*)(QKV + ((size_t)(b * Sn + m0 + r)) * 2048 + 512 + h * 64 + e0);
            int m = m0 + r;
            int i0 = e0 >> 1;
            float is0 = 1.0f / tscl[m * 32 + i0], is1 = 1.0f / tscl[m * 32 + i0 + 1];
            float c0 = tcos[m * 32 + i0] * is0, n0 = tsin[m * 32 + i0] * is0;
            float c1 = tcos[m * 32 + i0 + 1] * is1, n1 = tsin[m * 32 + i0 + 1] * is1;
            float k0 = v.x * c0 - v.y * n0;
            float k1 = v.y * c0 + v.x * n0;
            float k2 = v.z * c1 - v.w * n1;
            float k3 = v.w * c1 + v.z * n1;
            uint2 hu, lu;
            hu.x = pack_bf16_hi2(k0, k1, lu.x);
            hu.y = pack_bf16_hi2(k2, k3, lu.y);
            uint32_t off = (uint32_t)(r * 144 + e0 * 2);
            *(uint2*)(smc + AK + off)        = hu;
            *(uint2*)(smc + AK + 9216 + off) = lu;
        }
#pragma unroll
        for (int i = 0; i < 8; i++) {
            int f = i * 256 + tid;
            int r = f >> 5;
            int v0 = (f & 31) * 4;
            float4 v = *(const float4*)(QKV + ((size_t)(b * Sn + m0 + r)) * 2048 + 1024 + h * 128 + v0);
            uint2 hu, lu;
            hu.x = pack_bf16_hi2(v.x, v.y, lu.x);
            hu.y = pack_bf16_hi2(v.z, v.w, lu.y);
            uint32_t off = (uint32_t)(r * 272 + v0 * 2);
            *(uint2*)(smc + AVH + off) = hu;
            *(uint2*)(smc + AVL + off) = lu;
        }
        __syncthreads();

        float pacc[4][4];
#pragma unroll
        for (int i = 0; i < 4; i++)
#pragma unroll
            for (int j = 0; j < 4; j++) pacc[i][j] = 0.f;

        const uint32_t qbase = sb + AQ + ((wm * 16 + (lane & 15)) * 144 + (lane >> 4) * 16);
        const uint32_t kbase = sb + AK + ((wn * 32 + (lane & 15)) * 144 + (lane >> 4) * 16);
#pragma unroll
        for (int ks = 0; ks < 4; ks++) {
            uint32_t ah[4], al[4];
            ldsm4(ah[0], ah[1], ah[2], ah[3], qbase + ks * 32);
            ldsm4(al[0], al[1], al[2], al[3], qbase + 9216 + ks * 32);
            uint32_t r0, r1, r2, r3, u0, u1, u2, u3;
            ldsm4(r0, r1, r2, r3, kbase + ks * 32);
            ldsm4(u0, u1, u2, u3, kbase + 16 * 144 + ks * 32);
            uint32_t s0r, s1r, s2r, s3r, t0, t1, t2, t3;
            ldsm4(s0r, s1r, s2r, s3r, kbase + 9216 + ks * 32);
            ldsm4(t0, t1, t2, t3, kbase + 9216 + 16 * 144 + ks * 32);
            uint32_t bhx[4][2] = {{r0, r2}, {r1, r3}, {u0, u2}, {u1, u3}};
            uint32_t blx[4][2] = {{s0r, s2r}, {s1r, s3r}, {t0, t2}, {t1, t3}};
#pragma unroll
            for (int nt = 0; nt < 4; nt++) mma_bf16(pacc[nt], ah, bhx[nt]);
#pragma unroll
            for (int nt = 0; nt < 4; nt++) mma_bf16(pacc[nt], al, bhx[nt]);
#pragma unroll
            for (int nt = 0; nt < 4; nt++) mma_bf16(pacc[nt], ah, blx[nt]);
        }

#pragma unroll
        for (int nt = 0; nt < 4; nt++) {
#pragma unroll
            for (int half = 0; half < 2; half++) {
                int s_loc = wm * 16 + (lane >> 2) + half * 8;
                int m_loc = wn * 32 + nt * 8 + (lane & 3) * 2;
                int d0 = (s0 + s_loc) - (m0 + m_loc);
                float c0 = pacc[nt][half * 2];
                float c1 = pacc[nt][half * 2 + 1];
                float v0 = (d0 >= 0)     ? c0 * exp2f((float)d0 * lg) : 0.f;
                float v1 = (d0 - 1 >= 0) ? c1 * exp2f((float)(d0 - 1) * lg) : 0.f;
                uint32_t lo;
                uint32_t hi = pack_bf16_hi2(v0, v1, lo);
                uint32_t off = (uint32_t)(s_loc * 144 + m_loc * 2);
                *(uint32_t*)(smc + AP + off)        = hi;
                *(uint32_t*)(smc + AP + 9216 + off) = lo;
            }
        }
        __syncthreads();

        const uint32_t pbase = sb + AP + ((wm * 16 + (lane & 15)) * 144 + (lane >> 4) * 16);
#pragma unroll
        for (int ks = 0; ks < 4; ks++) {
            uint32_t ah[4], al[4];
            ldsm4(ah[0], ah[1], ah[2], ah[3], pbase + ks * 32);
            ldsm4(al[0], al[1], al[2], al[3], pbase + 9216 + ks * 32);
            const uint32_t vrow = (uint32_t)((ks * 16 + (lane & 15)) * 272);
#pragma unroll
            for (int vg = 0; vg < 4; vg++) {
                uint32_t voff = (uint32_t)((wn * 64 + vg * 16 + (lane >> 4) * 8) * 2);
                uint32_t r0, r1, r2, r3, q0, q1, q2, q3;
                ldsm4t(r0, r1, r2, r3, sb + AVH + vrow + voff);
                ldsm4t(q0, q1, q2, q3, sb + AVL + vrow + voff);
                uint32_t vh0[2] = {r0, r1}, vh1[2] = {r2, r3};
                uint32_t vl0[2] = {q0, q1}, vl1[2] = {q2, q3};
                float* y0 = yacc[2 * vg];
                float* y1 = yacc[2 * vg + 1];
                mma_bf16(y0, ah, vh0);
                mma_bf16(y1, ah, vh1);
                mma_bf16(y0, al, vh0);
                mma_bf16(y1, al, vh1);
                mma_bf16(y0, ah, vl0);
                mma_bf16(y1, ah, vl1);
            }
        }
    }
    __syncthreads();

    float* ep = (float*)smc;
#pragma unroll
    for (int nt = 0; nt < 8; nt++) {
        int r = wm * 16 + (lane >> 2);
        int cc = wn * 64 + nt * 8 + (lane & 3) * 2;
        *(float2*)(ep + r * 132 + cc)       = make_float2(yacc[nt][0], yacc[nt][1]);
        *(float2*)(ep + (r + 8) * 132 + cc) = make_float2(yacc[nt][2], yacc[nt][3]);
    }
    __syncthreads();
#pragma unroll
    for (int i = 0; i < 8; i++) {
        int f = i * 256 + tid;
        int r = f >> 5;
        int c4 = (f & 31) * 4;
        float4 v = *(const float4*)(ep + r * 132 + c4);
        *(float4*)(Yp + ((size_t)(b * Sn + s0 + r)) * 1024 + h * 128 + c4) = v;
    }
}

__global__ void k_out(const float* __restrict__ Hh, const float* __restrict__ w,
                      const float* __restrict__ b, float* __restrict__ out)
{
    int gw   = (blockIdx.x * blockDim.x + threadIdx.x) >> 5;
    int lane = threadIdx.x & 31;
    if (gw >= Mn) return;
    const float* row = Hh + (size_t)gw * 512;
    float acc = 0.f;
#pragma unroll
    for (int q = 0; q < 4; q++) {
        int d = q * 128 + lane * 4;
        float4 hv = *(const float4*)(row + d);
        float4 wv = *(const float4*)(w + d);
        acc += hv.x * wv.x + hv.y * wv.y + hv.z * wv.z + hv.w * wv.w;
    }
#pragma unroll
    for (int o = 16; o > 0; o >>= 1) acc += __shfl_xor_sync(0xffffffffu, acc, o);
    if (lane == 0) out[gw] = acc + b[0];
}

// ---------------- launcher ----------------
extern "C" void kernel_launch(void* const* d_in, const int* in_sizes, int n_in,
                              void* d_out, int out_size)
{
    (void)in_sizes; (void)n_in; (void)out_size;
    const float* x      = (const float*)d_in[0];
    const float* t      = (const float*)d_in[1];
    const float* emb_W  = (const float*)d_in[2];
    const float* emb_b  = (const float*)d_in[3];
    const float* ln1_w  = (const float*)d_in[4];
    const float* ln1_b  = (const float*)d_in[5];
    const float* ln2_w  = (const float*)d_in[6];
    const float* ln2_b  = (const float*)d_in[7];
    const float* WQ     = (const float*)d_in[8];
    const float* WK     = (const float*)d_in[9];
    const float* WV     = (const float*)d_in[10];
    const float* WG     = (const float*)d_in[11];
    const float* WO     = (const float*)d_in[12];
    const float* gn_w   = (const float*)d_in[13];
    const float* gn_b   = (const float*)d_in[14];
    const float* f1_W   = (const float*)d_in[15];
    const float* f1_b   = (const float*)d_in[16];
    const float* f2_W   = (const float*)d_in[17];
    const float* f2_b   = (const float*)d_in[18];
    const float* h1_W   = (const float*)d_in[19];
    const float* h1_b   = (const float*)d_in[20];
    const float* wave_w = (const float*)d_in[21];
    const float* h2_W   = (const float*)d_in[22];
    const float* h2_b   = (const float*)d_in[23];
    const float* h3_W   = (const float*)d_in[24];
    const float* h3_b   = (const float*)d_in[25];
    float* out = (float*)d_out;

    float *X, *QKV, *Y, *Yr, *tsin, *tcos, *tscl, *lg2;
    __nv_bfloat16 *whi, *wlo, *Xnh, *Xnl, *GYh, *GYl, *F1h, *F1l;
    cudaGetSymbolAddress((void**)&X,   g_X);
    cudaGetSymbolAddress((void**)&QKV, g_QKV);
    cudaGetSymbolAddress((void**)&Y,   g_Y);
    cudaGetSymbolAddress((void**)&Yr,  g_Yr);
    cudaGetSymbolAddress((void**)&Xnh, g_Xnh);
    cudaGetSymbolAddress((void**)&Xnl, g_Xnl);
    cudaGetSymbolAddress((void**)&GYh, g_GYh);
    cudaGetSymbolAddress((void**)&GYl, g_GYl);
    cudaGetSymbolAddress((void**)&F1h, g_F1h);
    cudaGetSymbolAddress((void**)&F1l, g_F1l);
    cudaGetSymbolAddress((void**)&whi, g_whi);
    cudaGetSymbolAddress((void**)&wlo, g_wlo);
    cudaGetSymbolAddress((void**)&tsin, g_sin);
    cudaGetSymbolAddress((void**)&tcos, g_cos);
    cudaGetSymbolAddress((void**)&tscl, g_scl);
    cudaGetSymbolAddress((void**)&lg2,  g_lg2);

    cudaFuncSetAttribute(k_gemm_s, cudaFuncAttributeMaxDynamicSharedMemorySize, GK_SMEM);
    cudaFuncSetAttribute(k_attn_mma, cudaFuncAttributeMaxDynamicSharedMemorySize, AT_SMEM);

    k_embed_ln<<<Mn / 8, 256>>>(x, t, emb_W, emb_b, X, Xnh, Xnl, ln1_w, ln1_b);
    // single consolidated weight-prep launch (replaces 9 k_prepw launches)
    k_prepw_all<<<dim3(2048, 9, 4), 256>>>(WQ, WK, WV, WG, WO, f1_W, f2_W, h1_W, h2_W,
                                           whi, wlo);
    // fused QKV projection for layer 0
    k_gemm_s<<<dim3(16, 512), 256, GK_SMEM>>>(Xnh, Xnl, whi + OFF_WQ, wlo + OFF_WQ,
                                              QKV, nullptr, nullptr, Mn, 2048, 512,
                                              nullptr, nullptr, nullptr, 0, EPI_NONE);
    k_tables<<<32, 256>>>(tsin, tcos, tscl, lg2);

    for (int l = 0; l < Ln; l++) {
        size_t lw = (size_t)l * LSW;
        if (l > 0) {
            k_ln<<<Mn / 8, 256>>>(X, Xnh, Xnl, ln1_w + l * Dn, ln1_b + l * Dn);
            k_gemm_s<<<dim3(16, 512), 256, GK_SMEM>>>(Xnh, Xnl, whi + lw + OFF_WQ, wlo + lw + OFF_WQ,
                                                      QKV, nullptr, nullptr, Mn, 2048, 512,
                                                      nullptr, nullptr, nullptr, 0, EPI_NONE);
        }
        k_attn_mma<<<dim3(4, Bn * Hn), 256, AT_SMEM>>>(QKV, Y, tsin, tcos, tscl, lg2);
        // WG GEMM with fused GroupNorm on Y (extra): bias=gn_w, wptr=gn_b
        k_gemm_s<<<dim3(8, 512), 256, GK_SMEM>>>(Xnh, Xnl, whi + lw + OFF_WG, wlo + lw + OFF_WG,
                                                 nullptr, GYh, GYl, Mn, 1024, 512,
                                                 gn_w + l * Vn, Y, gn_b + l * Vn, 0, EPI_GN_SILU_MUL);
        k_gemm_s<<<dim3(4, 512), 256, GK_SMEM>>>(GYh, GYl, whi + lw + OFF_WO, wlo + lw + OFF_WO,
                                                 Yr, nullptr, nullptr, Mn, 512, 1024,
                                                 nullptr, X, nullptr, 0, EPI_ADD_RES);
        k_ln<<<Mn / 8, 256>>>(Yr, Xnh, Xnl, ln2_w + l * Dn, ln2_b + l * Dn);
        k_gemm_s<<<dim3(1, 512), 256, GK_SMEM>>>(Xnh, Xnl, whi + lw + OFF_F1, wlo + lw + OFF_F1,
                                                 nullptr, F1h, F1l, Mn, 128, 512,
                                                 f1_b + l * FFNn, nullptr, nullptr, 0, EPI_BIAS_GELU);
        // last layer: also emit bf16 hi/lo of X for the head
        k_gemm_s<<<dim3(4, 512), 256, GK_SMEM>>>(F1h, F1l, whi + lw + OFF_F2, wlo + lw + OFF_F2,
                                                 X, (l == Ln - 1) ? GYh : nullptr,
                                                 (l == Ln - 1) ? GYl : nullptr, Mn, 512, 128,
                                                 f2_b + l * Dn, Yr, nullptr, 0, EPI_BIAS_ADD_RES);
    }

    // head
    k_gemm_s<<<dim3(4, 512), 256, GK_SMEM>>>(GYh, GYl, whi + OFF_H1, wlo + OFF_H1,
                                             nullptr, Xnh, Xnl, Mn, 512, 512,
                                             h1_b, nullptr, wave_w, 0, EPI_BIAS_WAVE);
    k_gemm_s<<<dim3(4, 512), 256, GK_SMEM>>>(Xnh, Xnl, whi + OFF_H2, wlo + OFF_H2,
                                             QKV, nullptr, nullptr, Mn, 512, 512,
                                             h2_b, nullptr, wave_w, 2, EPI_BIAS_WAVE);
    k_out<<<Mn / 8, 256>>>(QKV, h3_W, h3_b, out);
}

// round 16
// speedup vs baseline: 1.0092x; 1.0092x over previous
#include <cuda_runtime.h>
#include <cuda_bf16.h>
#include <math.h>
#include <stdint.h>

// ---------------- problem dims ----------------
#define Bn   256
#define Sn   256
#define Dn   512
#define Hn   8
#define Vn   1024
#define Ln   4
#define FFNn 128
#define Mn   (Bn*Sn)

// ---------------- scratch ----------------
__device__ float g_X  [33554432];
__device__ float g_Y  [67108864];    // attn out fp32 (also head H2 out)
__device__ float g_Yr [33554432];
__device__ __nv_bfloat16 g_QKVh[134217728];  // Mn*2048 rotated+split Q|K|V hi
__device__ __nv_bfloat16 g_QKVl[134217728];  // lo
__device__ __nv_bfloat16 g_Xnh[33554432];
__device__ __nv_bfloat16 g_Xnl[33554432];
__device__ __nv_bfloat16 g_GYh[67108864];
__device__ __nv_bfloat16 g_GYl[67108864];
__device__ __nv_bfloat16 g_F1h[8388608];
__device__ __nv_bfloat16 g_F1l[8388608];
__device__ __nv_bfloat16 g_whi[9437184];
__device__ __nv_bfloat16 g_wlo[9437184];
__device__ float g_sin[8192];
__device__ float g_cos[8192];
__device__ float g_scl[8192];
__device__ float g_lg2[8];

#define LSW    2228224
#define OFF_WQ 0
#define OFF_WK 262144
#define OFF_WV 524288
#define OFF_WG 1048576
#define OFF_WO 1572864
#define OFF_F1 2097152
#define OFF_F2 2162688
#define OFF_H1 8912896
#define OFF_H2 9175040

#define EPI_NONE          0
#define EPI_SILU_MUL      1
#define EPI_ADD_RES       2
#define EPI_BIAS_GELU     3
#define EPI_BIAS_ADD_RES  4
#define EPI_BIAS_WAVE     5
#define EPI_GN_SILU_MUL   6
#define EPI_ROPE_SPLIT    7

// ---------------- PTX helpers ----------------
__device__ __forceinline__ uint32_t smem_u32(const void* p) {
    uint32_t a;
    asm("{ .reg .u64 t; cvta.to.shared.u64 t, %1; cvt.u32.u64 %0, t; }" : "=r"(a) : "l"(p));
    return a;
}
__device__ __forceinline__ void ldsm4(uint32_t& r0, uint32_t& r1, uint32_t& r2, uint32_t& r3,
                                      uint32_t addr) {
    asm volatile("ldmatrix.sync.aligned.m8n8.x4.shared.b16 {%0,%1,%2,%3}, [%4];"
                 : "=r"(r0), "=r"(r1), "=r"(r2), "=r"(r3) : "r"(addr));
}
__device__ __forceinline__ void ldsm4t(uint32_t& r0, uint32_t& r1, uint32_t& r2, uint32_t& r3,
                                       uint32_t addr) {
    asm volatile("ldmatrix.sync.aligned.m8n8.x4.trans.shared.b16 {%0,%1,%2,%3}, [%4];"
                 : "=r"(r0), "=r"(r1), "=r"(r2), "=r"(r3) : "r"(addr));
}
__device__ __forceinline__ void mma_bf16(float* c, const uint32_t* a, const uint32_t* b) {
    asm volatile(
        "mma.sync.aligned.m16n8k16.row.col.f32.bf16.bf16.f32 "
        "{%0,%1,%2,%3}, {%4,%5,%6,%7}, {%8,%9}, {%0,%1,%2,%3};"
        : "+f"(c[0]), "+f"(c[1]), "+f"(c[2]), "+f"(c[3])
        : "r"(a[0]), "r"(a[1]), "r"(a[2]), "r"(a[3]), "r"(b[0]), "r"(b[1]));
}
__device__ __forceinline__ void cpa16(uint32_t dst, const void* src) {
    asm volatile("cp.async.cg.shared.global [%0], [%1], 16;" :: "r"(dst), "l"(src));
}
__device__ __forceinline__ void cpa_commit() {
    asm volatile("cp.async.commit_group;" ::: "memory");
}
template<int NN> __device__ __forceinline__ void cpa_wait() {
    asm volatile("cp.async.wait_group %0;" :: "n"(NN) : "memory");
}
__device__ __forceinline__ uint32_t pack_bf16_hi2(float a, float b, uint32_t& lo) {
    __nv_bfloat16 h0 = __float2bfloat16(a);
    __nv_bfloat16 h1 = __float2bfloat16(b);
    __nv_bfloat16 l0 = __float2bfloat16(a - __bfloat162float(h0));
    __nv_bfloat16 l1 = __float2bfloat16(b - __bfloat162float(h1));
    lo = (uint32_t)__bfloat16_as_ushort(l0) | ((uint32_t)__bfloat16_as_ushort(l1) << 16);
    return (uint32_t)__bfloat16_as_ushort(h0) | ((uint32_t)__bfloat16_as_ushort(h1) << 16);
}

// ---------------- small kernels ----------------
__global__ void k_tables(float* __restrict__ st, float* __restrict__ ct,
                         float* __restrict__ sc, float* __restrict__ lg)
{
    int idx = blockIdx.x * blockDim.x + threadIdx.x;
    if (idx < Sn * 32) {
        int s = idx >> 5, i = idx & 31;
        float sv = (2.0f * (float)i + 0.4f * 64.0f) / (1.4f * 64.0f);
        sc[idx] = powf(sv, (float)s / 512.0f);
        float invf = powf(10000.0f, -(float)i / 32.0f);
        float ang = (float)s * invf;
        st[idx] = sinf(ang);
        ct[idx] = cosf(ang);
    }
    if (idx < Hn) {
        float l0 = logf(1.0f / 32.0f);
        float l1 = logf(1.0f / 512.0f);
        float lj = l0 + (float)idx * (l1 - l0) / 7.0f;
        float gamma = 1.0f - expf(lj);
        lg[idx] = log2f(gamma);
    }
}

// consolidated weight-prep: grid.y = weight type, grid.z = layer
__global__ void k_prepw_all(const float* __restrict__ WQ, const float* __restrict__ WK,
                            const float* __restrict__ WV, const float* __restrict__ WG,
                            const float* __restrict__ WO, const float* __restrict__ F1w,
                            const float* __restrict__ F2w, const float* __restrict__ H1w,
                            const float* __restrict__ H2w,
                            __nv_bfloat16* __restrict__ hi, __nv_bfloat16* __restrict__ lo)
{
    const int wtype = blockIdx.y;
    const int l = blockIdx.z;
    const float* src;
    int Nn, Kk, mode;
    long srcStride;
    size_t dof;
    switch (wtype) {
        case 0: src = WQ;  Nn = 512;  Kk = 512;  mode = 1; srcStride = 262144; dof = OFF_WQ + (size_t)l * LSW; break;
        case 1: src = WK;  Nn = 512;  Kk = 512;  mode = 1; srcStride = 262144; dof = OFF_WK + (size_t)l * LSW; break;
        case 2: src = WV;  Nn = 1024; Kk = 512;  mode = 2; srcStride = 524288; dof = OFF_WV + (size_t)l * LSW; break;
        case 3: src = WG;  Nn = 1024; Kk = 512;  mode = 0; srcStride = 524288; dof = OFF_WG + (size_t)l * LSW; break;
        case 4: src = WO;  Nn = 512;  Kk = 1024; mode = 0; srcStride = 524288; dof = OFF_WO + (size_t)l * LSW; break;
        case 5: src = F1w; Nn = 128;  Kk = 512;  mode = 0; srcStride = 65536;  dof = OFF_F1 + (size_t)l * LSW; break;
        case 6: src = F2w; Nn = 512;  Kk = 128;  mode = 0; srcStride = 65536;  dof = OFF_F2 + (size_t)l * LSW; break;
        case 7: if (l != 0) return;
                src = H1w; Nn = 512;  Kk = 512;  mode = 0; srcStride = 0;      dof = OFF_H1; break;
        default: if (l != 0) return;
                src = H2w; Nn = 512;  Kk = 512;  mode = 0; srcStride = 0;      dof = OFF_H2; break;
    }
    int idx = blockIdx.x * blockDim.x + threadIdx.x;
    if (idx >= Nn * Kk) return;
    const float* s = src + (size_t)l * srcStride;
    int n = idx / Kk, k = idx % Kk;
    float v;
    if (mode == 0) v = s[(size_t)k * Nn + n];
    else if (mode == 1) { int h = n >> 6, e = n & 63;  v = s[((size_t)h * Kk + k) * 64 + e]; }
    else                { int h = n >> 7, vv = n & 127; v = s[((size_t)h * Kk + k) * 128 + vv]; }
    __nv_bfloat16 hv = __float2bfloat16(v);
    __nv_bfloat16 lv = __float2bfloat16(v - __bfloat162float(hv));
    hi[dof + idx] = hv;
    lo[dof + idx] = lv;
}

// fused embed + layer-0 layernorm (warp per token)
__global__ void k_embed_ln(const float* __restrict__ x, const float* __restrict__ t,
                           const float* __restrict__ eW, const float* __restrict__ eb,
                           float* __restrict__ X,
                           __nv_bfloat16* __restrict__ Ohi, __nv_bfloat16* __restrict__ Olo,
                           const float* __restrict__ w, const float* __restrict__ b)
{
    int gw   = (blockIdx.x * blockDim.x + threadIdx.x) >> 5;
    int lane = threadIdx.x & 31;
    if (gw >= Mn) return;
    float xv = x[gw], tv = t[gw];
    float4 v[4];
    float s = 0.f, ss = 0.f;
#pragma unroll
    for (int q = 0; q < 4; q++) {
        int d = q * 128 + lane * 4;
        float4 w0 = *(const float4*)(eW + d);
        float4 w1 = *(const float4*)(eW + Dn + d);
        float4 bb = *(const float4*)(eb + d);
        v[q].x = xv * w0.x + tv * w1.x + bb.x;
        v[q].y = xv * w0.y + tv * w1.y + bb.y;
        v[q].z = xv * w0.z + tv * w1.z + bb.z;
        v[q].w = xv * w0.w + tv * w1.w + bb.w;
        *(float4*)(X + (size_t)gw * 512 + d) = v[q];
        s  += v[q].x + v[q].y + v[q].z + v[q].w;
        ss += v[q].x * v[q].x + v[q].y * v[q].y + v[q].z * v[q].z + v[q].w * v[q].w;
    }
#pragma unroll
    for (int o = 16; o > 0; o >>= 1) {
        s  += __shfl_xor_sync(0xffffffffu, s,  o);
        ss += __shfl_xor_sync(0xffffffffu, ss, o);
    }
    float mu  = s * (1.0f / 512.0f);
    float var = ss * (1.0f / 512.0f) - mu * mu;
    float rs  = rsqrtf(var + 1e-5f);
#pragma unroll
    for (int q = 0; q < 4; q++) {
        int d = q * 128 + lane * 4;
        float4 wv = *(const float4*)(w + d);
        float4 bv = *(const float4*)(b + d);
        float o0 = (v[q].x - mu) * rs * wv.x + bv.x;
        float o1 = (v[q].y - mu) * rs * wv.y + bv.y;
        float o2 = (v[q].z - mu) * rs * wv.z + bv.z;
        float o3 = (v[q].w - mu) * rs * wv.w + bv.w;
        uint2 hu, lu;
        hu.x = pack_bf16_hi2(o0, o1, lu.x);
        hu.y = pack_bf16_hi2(o2, o3, lu.y);
        *(uint2*)(Ohi + (size_t)gw * 512 + d) = hu;
        *(uint2*)(Olo + (size_t)gw * 512 + d) = lu;
    }
}

__global__ void k_ln(const float* __restrict__ Xin, __nv_bfloat16* __restrict__ Ohi,
                     __nv_bfloat16* __restrict__ Olo,
                     const float* __restrict__ w, const float* __restrict__ b)
{
    int gw   = (blockIdx.x * blockDim.x + threadIdx.x) >> 5;
    int lane = threadIdx.x & 31;
    if (gw >= Mn) return;
    const float* row = Xin + (size_t)gw * 512;
    float4 v[4];
    float s = 0.f, ss = 0.f;
#pragma unroll
    for (int q = 0; q < 4; q++) {
        v[q] = *(const float4*)(row + q * 128 + lane * 4);
        s  += v[q].x + v[q].y + v[q].z + v[q].w;
        ss += v[q].x * v[q].x + v[q].y * v[q].y + v[q].z * v[q].z + v[q].w * v[q].w;
    }
#pragma unroll
    for (int o = 16; o > 0; o >>= 1) {
        s  += __shfl_xor_sync(0xffffffffu, s,  o);
        ss += __shfl_xor_sync(0xffffffffu, ss, o);
    }
    float mu  = s * (1.0f / 512.0f);
    float var = ss * (1.0f / 512.0f) - mu * mu;
    float rs  = rsqrtf(var + 1e-5f);
#pragma unroll
    for (int q = 0; q < 4; q++) {
        int d = q * 128 + lane * 4;
        float4 wv = *(const float4*)(w + d);
        float4 bv = *(const float4*)(b + d);
        float o0 = (v[q].x - mu) * rs * wv.x + bv.x;
        float o1 = (v[q].y - mu) * rs * wv.y + bv.y;
        float o2 = (v[q].z - mu) * rs * wv.z + bv.z;
        float o3 = (v[q].w - mu) * rs * wv.w + bv.w;
        uint2 hu, lu;
        hu.x = pack_bf16_hi2(o0, o1, lu.x);
        hu.y = pack_bf16_hi2(o2, o3, lu.y);
        *(uint2*)(Ohi + (size_t)gw * 512 + d) = hu;
        *(uint2*)(Olo + (size_t)gw * 512 + d) = lu;
    }
}

// ================= GEMM (R12 config + EPI_ROPE_SPLIT) =================
#define STG   24576
#define GK_SMEM (4*STG)
#define GSTR 24
__global__ void __launch_bounds__(256, 2) k_gemm_s(
    const __nv_bfloat16* __restrict__ Ahi, const __nv_bfloat16* __restrict__ Alo,
    const __nv_bfloat16* __restrict__ Bhi, const __nv_bfloat16* __restrict__ Blo,
    float* __restrict__ Cf, __nv_bfloat16* __restrict__ Chi, __nv_bfloat16* __restrict__ Clo,
    const int M, const int N, const int K,
    const float* __restrict__ bias, const float* __restrict__ extra,
    const float* __restrict__ wptr, const int woff, const int epi)
{
    extern __shared__ char smc[];
    const uint32_t sb = smem_u32(smc);
    const int tid = threadIdx.x;
    const int lane = tid & 31;
    const int wid = tid >> 5;
    const int wm = wid & 3;
    const int wn = wid >> 2;
    const int m0 = blockIdx.y * 128;
    const int n0 = blockIdx.x * 128;

    float acc[16][4];
#pragma unroll
    for (int i = 0; i < 16; i++)
#pragma unroll
        for (int j = 0; j < 4; j++) acc[i][j] = 0.f;

    const int nch = K >> 4;
    const int row  = tid >> 1;
    const int hcol = (tid & 1) * 8;
    const uint32_t sdst = (uint32_t)((row * GSTR + hcol) * 2);
    const __nv_bfloat16* gA  = Ahi + (size_t)(m0 + row) * K + hcol;
    const __nv_bfloat16* gAl = Alo + (size_t)(m0 + row) * K + hcol;
    const __nv_bfloat16* gB  = Bhi + (size_t)(n0 + row) * K + hcol;
    const __nv_bfloat16* gBl = Blo + (size_t)(n0 + row) * K + hcol;

#define ISSUE(c) do {                                   \
        const uint32_t stb = sb + ((c) & 3) * STG;      \
        const int ko = (c) * 16;                        \
        cpa16(stb + sdst,          gA  + ko);           \
        cpa16(stb +  6144 + sdst,  gAl + ko);           \
        cpa16(stb + 12288 + sdst,  gB  + ko);           \
        cpa16(stb + 18432 + sdst,  gBl + ko);           \
    } while (0)

    ISSUE(0); cpa_commit();
    ISSUE(1); cpa_commit();
    ISSUE(2); cpa_commit();

    const int a_lo = (wm * 32 + (lane & 15)) * GSTR + (lane >> 4) * 8;
    const int b_lo = (wn * 64 + (lane & 15)) * GSTR + (lane >> 4) * 8;

    for (int c = 0; c < nch; c++) {
        cpa_wait<2>();
        __syncthreads();
        if (c + 3 < nch) ISSUE(c + 3);
        cpa_commit();

        const uint32_t st = (c & 3) * STG;
        const uint32_t abase = sb + st + a_lo * 2;
        const uint32_t bbase = sb + st + 12288 + b_lo * 2;

        uint32_t ah[2][4], al[2][4];
#pragma unroll
        for (int mt = 0; mt < 2; mt++)
            ldsm4(ah[mt][0], ah[mt][1], ah[mt][2], ah[mt][3], abase + mt * 16 * GSTR * 2);
#pragma unroll
        for (int mt = 0; mt < 2; mt++)
            ldsm4(al[mt][0], al[mt][1], al[mt][2], al[mt][3], abase + 6144 + mt * 16 * GSTR * 2);

#pragma unroll
        for (int nt2 = 0; nt2 < 4; nt2++) {
            uint32_t r0, r1, r2, r3, s0, s1, s2, s3;
            ldsm4(r0, r1, r2, r3, bbase + nt2 * 16 * GSTR * 2);
            ldsm4(s0, s1, s2, s3, bbase + 6144 + nt2 * 16 * GSTR * 2);
            uint32_t bh0[2] = {r0, r2}, bh1[2] = {r1, r3};
            uint32_t bl0[2] = {s0, s2}, bl1[2] = {s1, s3};
#pragma unroll
            for (int mt = 0; mt < 2; mt++) {
                float* a0 = acc[mt * 8 + 2 * nt2];
                float* a1 = acc[mt * 8 + 2 * nt2 + 1];
                mma_bf16(a0, ah[mt], bh0);
                mma_bf16(a1, ah[mt], bh1);
                mma_bf16(a0, al[mt], bh0);
                mma_bf16(a1, al[mt], bh1);
                mma_bf16(a0, ah[mt], bl0);
                mma_bf16(a1, ah[mt], bl1);
            }
        }
    }
    cpa_wait<0>();
    __syncthreads();

    float* ep = (float*)smc;
#pragma unroll
    for (int mt = 0; mt < 2; mt++)
#pragma unroll
        for (int nt = 0; nt < 8; nt++) {
            int r = wm * 32 + mt * 16 + (lane >> 2);
            int cc = wn * 64 + nt * 8 + (lane & 3) * 2;
            *(float2*)(ep + r * 132 + cc) = make_float2(acc[mt * 8 + nt][0], acc[mt * 8 + nt][1]);
            *(float2*)(ep + (r + 8) * 132 + cc) = make_float2(acc[mt * 8 + nt][2], acc[mt * 8 + nt][3]);
        }
    __syncthreads();

    float w0 = 0.f, w1 = 0.f;
    if (epi == EPI_BIAS_WAVE) { w0 = wptr[woff]; w1 = wptr[woff + 1]; }
#pragma unroll 1
    for (int i = 0; i < 16; i++) {
        int f = i * 256 + tid;
        int r = f >> 5;
        int c4 = (f & 31) * 4;
        float4 v = *(const float4*)(ep + r * 132 + c4);
        size_t base = (size_t)(m0 + r) * N + n0 + c4;
        if (epi == EPI_SILU_MUL) {
            float4 e = *(const float4*)(extra + base);
            v.x = v.x * e.x / (1.0f + expf(-v.x));
            v.y = v.y * e.y / (1.0f + expf(-v.y));
            v.z = v.z * e.z / (1.0f + expf(-v.z));
            v.w = v.w * e.w / (1.0f + expf(-v.w));
        } else if (epi == EPI_GN_SILU_MUL) {
            float4 e = *(const float4*)(extra + base);
            float s  = e.x + e.y + e.z + e.w;
            float ss = e.x * e.x + e.y * e.y + e.z * e.z + e.w * e.w;
#pragma unroll
            for (int o = 16; o > 0; o >>= 1) {
                s  += __shfl_xor_sync(0xffffffffu, s,  o);
                ss += __shfl_xor_sync(0xffffffffu, ss, o);
            }
            float mu  = s * (1.0f / 128.0f);
            float var = ss * (1.0f / 128.0f) - mu * mu;
            float rs  = rsqrtf(var + 1e-5f);
            float4 gwv = *(const float4*)(bias + n0 + c4);
            float4 gbv = *(const float4*)(wptr + n0 + c4);
            float n0v = (e.x - mu) * rs * gwv.x + gbv.x;
            float n1v = (e.y - mu) * rs * gwv.y + gbv.y;
            float n2v = (e.z - mu) * rs * gwv.z + gbv.z;
            float n3v = (e.w - mu) * rs * gwv.w + gbv.w;
            v.x = v.x * n0v / (1.0f + expf(-v.x));
            v.y = v.y * n1v / (1.0f + expf(-v.y));
            v.z = v.z * n2v / (1.0f + expf(-v.z));
            v.w = v.w * n3v / (1.0f + expf(-v.w));
        } else if (epi == EPI_ADD_RES) {
            float4 e = *(const float4*)(extra + base);
            v.x += e.x; v.y += e.y; v.z += e.z; v.w += e.w;
        } else if (epi == EPI_BIAS_GELU) {
            float4 bb = *(const float4*)(bias + n0 + c4);
            v.x += bb.x; v.y += bb.y; v.z += bb.z; v.w += bb.w;
            v.x = 0.5f * v.x * (1.0f + erff(v.x * 0.70710678118f));
            v.y = 0.5f * v.y * (1.0f + erff(v.y * 0.70710678118f));
            v.z = 0.5f * v.z * (1.0f + erff(v.z * 0.70710678118f));
            v.w = 0.5f * v.w * (1.0f + erff(v.w * 0.70710678118f));
        } else if (epi == EPI_BIAS_ADD_RES) {
            float4 bb = *(const float4*)(bias + n0 + c4);
            float4 e  = *(const float4*)(extra + base);
            v.x += bb.x + e.x; v.y += bb.y + e.y; v.z += bb.z + e.z; v.w += bb.w + e.w;
        } else if (epi == EPI_BIAS_WAVE) {
            float4 bb = *(const float4*)(bias + n0 + c4);
            v.x += bb.x; v.y += bb.y; v.z += bb.z; v.w += bb.w;
            v.x = w0 * sinf(v.x) + w1 * cosf(v.x);
            v.y = w0 * sinf(v.y) + w1 * cosf(v.y);
            v.z = w0 * sinf(v.z) + w1 * cosf(v.z);
            v.w = w0 * sinf(v.w) + w1 * cosf(v.w);
        } else if (epi == EPI_ROPE_SPLIT) {
            // bias=tsin, wptr=tcos, extra=tscl; cols [0,512)=Q (×scale), [512,1024)=K (×1/scale), rest V
            int nn = n0 + c4;
            if (nn < 1024) {
                int srow = (m0 + r) & (Sn - 1);
                int i0 = (nn & 63) >> 1;
                float sc0 = extra[srow * 32 + i0];
                float sc1 = extra[srow * 32 + i0 + 1];
                if (nn >= 512) { sc0 = 1.0f / sc0; sc1 = 1.0f / sc1; }
                float c0 = wptr[srow * 32 + i0] * sc0;
                float s0v = bias[srow * 32 + i0] * sc0;
                float c1 = wptr[srow * 32 + i0 + 1] * sc1;
                float s1v = bias[srow * 32 + i0 + 1] * sc1;
                float t0 = v.x * c0 - v.y * s0v;
                float t1 = v.y * c0 + v.x * s0v;
                float t2 = v.z * c1 - v.w * s1v;
                float t3 = v.w * c1 + v.z * s1v;
                v.x = t0; v.y = t1; v.z = t2; v.w = t3;
            }
        }
        if (Cf) *(float4*)(Cf + base) = v;
        if (Chi) {
            uint2 hu, lu;
            hu.x = pack_bf16_hi2(v.x, v.y, lu.x);
            hu.y = pack_bf16_hi2(v.z, v.w, lu.y);
            *(uint2*)(Chi + base) = hu;
            *(uint2*)(Clo + base) = lu;
        }
    }
#undef ISSUE
}

// ================= HMMA split-bf16 retention attention (pre-split QKV input) =================
#define AT_SMEM 90112
#define AQ  0
#define AK  18432
#define AP  36864
#define AVH 55296
#define AVL 72704
__global__ void __launch_bounds__(256, 2) k_attn_mma(
    const __nv_bfloat16* __restrict__ QKVh, const __nv_bfloat16* __restrict__ QKVl,
    float* __restrict__ Yp, const float* __restrict__ lg2)
{
    extern __shared__ char smc[];
    const uint32_t sb = smem_u32(smc);
    const int st = blockIdx.x;
    const int bh = blockIdx.y;
    const int b = bh >> 3, h = bh & 7;
    const float lg = lg2[h];
    const int tid = threadIdx.x;
    const int lane = tid & 31;
    const int wid = tid >> 5;
    const int wm = wid & 3;
    const int wn = wid >> 2;
    const int s0 = st * 64;

    // Q tile: plain bf16 copies (rotation/split already done in QKV epilogue)
#pragma unroll
    for (int i = 0; i < 4; i++) {
        int f = i * 256 + tid;
        int r = f >> 4;
        int e0 = (f & 15) * 4;
        size_t g = ((size_t)(b * Sn + s0 + r)) * 2048 + h * 64 + e0;
        uint2 hu = *(const uint2*)(QKVh + g);
        uint2 lu = *(const uint2*)(QKVl + g);
        uint32_t off = (uint32_t)(r * 144 + e0 * 2);
        *(uint2*)(smc + AQ + off)        = hu;
        *(uint2*)(smc + AQ + 9216 + off) = lu;
    }

    float yacc[8][4];
#pragma unroll
    for (int i = 0; i < 8; i++)
#pragma unroll
        for (int j = 0; j < 4; j++) yacc[i][j] = 0.f;

    for (int mt = 0; mt <= st; mt++) {
        const int m0 = mt * 64;
        __syncthreads();
#pragma unroll
        for (int i = 0; i < 4; i++) {
            int f = i * 256 + tid;
            int r = f >> 4;
            int e0 = (f & 15) * 4;
            size_t g = ((size_t)(b * Sn + m0 + r)) * 2048 + 512 + h * 64 + e0;
            uint2 hu = *(const uint2*)(QKVh + g);
            uint2 lu = *(const uint2*)(QKVl + g);
            uint32_t off = (uint32_t)(r * 144 + e0 * 2);
            *(uint2*)(smc + AK + off)        = hu;
            *(uint2*)(smc + AK + 9216 + off) = lu;
        }
#pragma unroll
        for (int i = 0; i < 8; i++) {
            int f = i * 256 + tid;
            int r = f >> 5;
            int v0 = (f & 31) * 4;
            size_t g = ((size_t)(b * Sn + m0 + r)) * 2048 + 1024 + h * 128 + v0;
            uint2 hu = *(const uint2*)(QKVh + g);
            uint2 lu = *(const uint2*)(QKVl + g);
            uint32_t off = (uint32_t)(r * 272 + v0 * 2);
            *(uint2*)(smc + AVH + off) = hu;
            *(uint2*)(smc + AVL + off) = lu;
        }
        __syncthreads();

        float pacc[4][4];
#pragma unroll
        for (int i = 0; i < 4; i++)
#pragma unroll
            for (int j = 0; j < 4; j++) pacc[i][j] = 0.f;

        const uint32_t qbase = sb + AQ + ((wm * 16 + (lane & 15)) * 144 + (lane >> 4) * 16);
        const uint32_t kbase = sb + AK + ((wn * 32 + (lane & 15)) * 144 + (lane >> 4) * 16);
#pragma unroll
        for (int ks = 0; ks < 4; ks++) {
            uint32_t ah[4], al[4];
            ldsm4(ah[0], ah[1], ah[2], ah[3], qbase + ks * 32);
            ldsm4(al[0], al[1], al[2], al[3], qbase + 9216 + ks * 32);
            uint32_t r0, r1, r2, r3, u0, u1, u2, u3;
            ldsm4(r0, r1, r2, r3, kbase + ks * 32);
            ldsm4(u0, u1, u2, u3, kbase + 16 * 144 + ks * 32);
            uint32_t s0r, s1r, s2r, s3r, t0, t1, t2, t3;
            ldsm4(s0r, s1r, s2r, s3r, kbase + 9216 + ks * 32);
            ldsm4(t0, t1, t2, t3, kbase + 9216 + 16 * 144 + ks * 32);
            uint32_t bhx[4][2] = {{r0, r2}, {r1, r3}, {u0, u2}, {u1, u3}};
            uint32_t blx[4][2] = {{s0r, s2r}, {s1r, s3r}, {t0, t2}, {t1, t3}};
#pragma unroll
            for (int nt = 0; nt < 4; nt++) mma_bf16(pacc[nt], ah, bhx[nt]);
#pragma unroll
            for (int nt = 0; nt < 4; nt++) mma_bf16(pacc[nt], al, bhx[nt]);
#pragma unroll
            for (int nt = 0; nt < 4; nt++) mma_bf16(pacc[nt], ah, blx[nt]);
        }

#pragma unroll
        for (int nt = 0; nt < 4; nt++) {
#pragma unroll
            for (int half = 0; half < 2; half++) {
                int s_loc = wm * 16 + (lane >> 2) + half * 8;
                int m_loc = wn * 32 + nt * 8 + (lane & 3) * 2;
                int d0 = (s0 + s_loc) - (m0 + m_loc);
                float c0 = pacc[nt][half * 2];
                float c1 = pacc[nt][half * 2 + 1];
                float v0 = (d0 >= 0)     ? c0 * exp2f((float)d0 * lg) : 0.f;
                float v1 = (d0 - 1 >= 0) ? c1 * exp2f((float)(d0 - 1) * lg) : 0.f;
                uint32_t lo;
                uint32_t hi = pack_bf16_hi2(v0, v1, lo);
                uint32_t off = (uint32_t)(s_loc * 144 + m_loc * 2);
                *(uint32_t*)(smc + AP + off)        = hi;
                *(uint32_t*)(smc + AP + 9216 + off) = lo;
            }
        }
        __syncthreads();

        const uint32_t pbase = sb + AP + ((wm * 16 + (lane & 15)) * 144 + (lane >> 4) * 16);
#pragma unroll
        for (int ks = 0; ks < 4; ks++) {
            uint32_t ah[4], al[4];
            ldsm4(ah[0], ah[1], ah[2], ah[3], pbase + ks * 32);
            ldsm4(al[0], al[1], al[2], al[3], pbase + 9216 + ks * 32);
            const uint32_t vrow = (uint32_t)((ks * 16 + (lane & 15)) * 272);
#pragma unroll
            for (int vg = 0; vg < 4; vg++) {
                uint32_t voff = (uint32_t)((wn * 64 + vg * 16 + (lane >> 4) * 8) * 2);
                uint32_t r0, r1, r2, r3, q0, q1, q2, q3;
                ldsm4t(r0, r1, r2, r3, sb + AVH + vrow + voff);
                ldsm4t(q0, q1, q2, q3, sb + AVL + vrow + voff);
                uint32_t vh0[2] = {r0, r1}, vh1[2] = {r2, r3};
                uint32_t vl0[2] = {q0, q1}, vl1[2] = {q2, q3};
                float* y0 = yacc[2 * vg];
                float* y1 = yacc[2 * vg + 1];
                mma_bf16(y0, ah, vh0);
                mma_bf16(y1, ah, vh1);
                mma_bf16(y0, al, vh0);
                mma_bf16(y1, al, vh1);
                mma_bf16(y0, ah, vl0);
                mma_bf16(y1, ah, vl1);
            }
        }
    }
    __syncthreads();

    float* ep = (float*)smc;
#pragma unroll
    for (int nt = 0; nt < 8; nt++) {
        int r = wm * 16 + (lane >> 2);
        int cc = wn * 64 + nt * 8 + (lane & 3) * 2;
        *(float2*)(ep + r * 132 + cc)       = make_float2(yacc[nt][0], yacc[nt][1]);
        *(float2*)(ep + (r + 8) * 132 + cc) = make_float2(yacc[nt][2], yacc[nt][3]);
    }
    __syncthreads();
#pragma unroll
    for (int i = 0; i < 8; i++) {
        int f = i * 256 + tid;
        int r = f >> 5;
        int c4 = (f & 31) * 4;
        float4 v = *(const float4*)(ep + r * 132 + c4);
        *(float4*)(Yp + ((size_t)(b * Sn + s0 + r)) * 1024 + h * 128 + c4) = v;
    }
}

__global__ void k_out(const float* __restrict__ Hh, const float* __restrict__ w,
                      const float* __restrict__ b, float* __restrict__ out)
{
    int gw   = (blockIdx.x * blockDim.x + threadIdx.x) >> 5;
    int lane = threadIdx.x & 31;
    if (gw >= Mn) return;
    const float* row = Hh + (size_t)gw * 512;
    float acc = 0.f;
#pragma unroll
    for (int q = 0; q < 4; q++) {
        int d = q * 128 + lane * 4;
        float4 hv = *(const float4*)(row + d);
        float4 wv = *(const float4*)(w + d);
        acc += hv.x * wv.x + hv.y * wv.y + hv.z * wv.z + hv.w * wv.w;
    }
#pragma unroll
    for (int o = 16; o > 0; o >>= 1) acc += __shfl_xor_sync(0xffffffffu, acc, o);
    if (lane == 0) out[gw] = acc + b[0];
}

// ---------------- launcher ----------------
extern "C" void kernel_launch(void* const* d_in, const int* in_sizes, int n_in,
                              void* d_out, int out_size)
{
    (void)in_sizes; (void)n_in; (void)out_size;
    const float* x      = (const float*)d_in[0];
    const float* t      = (const float*)d_in[1];
    const float* emb_W  = (const float*)d_in[2];
    const float* emb_b  = (const float*)d_in[3];
    const float* ln1_w  = (const float*)d_in[4];
    const float* ln1_b  = (const float*)d_in[5];
    const float* ln2_w  = (const float*)d_in[6];
    const float* ln2_b  = (const float*)d_in[7];
    const float* WQ     = (const float*)d_in[8];
    const float* WK     = (const float*)d_in[9];
    const float* WV     = (const float*)d_in[10];
    const float* WG     = (const float*)d_in[11];
    const float* WO     = (const float*)d_in[12];
    const float* gn_w   = (const float*)d_in[13];
    const float* gn_b   = (const float*)d_in[14];
    const float* f1_W   = (const float*)d_in[15];
    const float* f1_b   = (const float*)d_in[16];
    const float* f2_W   = (const float*)d_in[17];
    const float* f2_b   = (const float*)d_in[18];
    const float* h1_W   = (const float*)d_in[19];
    const float* h1_b   = (const float*)d_in[20];
    const float* wave_w = (const float*)d_in[21];
    const float* h2_W   = (const float*)d_in[22];
    const float* h2_b   = (const float*)d_in[23];
    const float* h3_W   = (const float*)d_in[24];
    const float* h3_b   = (const float*)d_in[25];
    float* out = (float*)d_out;

    float *X, *Y, *Yr, *tsin, *tcos, *tscl, *lg2;
    __nv_bfloat16 *whi, *wlo, *QKVh, *QKVl, *Xnh, *Xnl, *GYh, *GYl, *F1h, *F1l;
    cudaGetSymbolAddress((void**)&X,    g_X);
    cudaGetSymbolAddress((void**)&Y,    g_Y);
    cudaGetSymbolAddress((void**)&Yr,   g_Yr);
    cudaGetSymbolAddress((void**)&QKVh, g_QKVh);
    cudaGetSymbolAddress((void**)&QKVl, g_QKVl);
    cudaGetSymbolAddress((void**)&Xnh,  g_Xnh);
    cudaGetSymbolAddress((void**)&Xnl,  g_Xnl);
    cudaGetSymbolAddress((void**)&GYh,  g_GYh);
    cudaGetSymbolAddress((void**)&GYl,  g_GYl);
    cudaGetSymbolAddress((void**)&F1h,  g_F1h);
    cudaGetSymbolAddress((void**)&F1l,  g_F1l);
    cudaGetSymbolAddress((void**)&whi,  g_whi);
    cudaGetSymbolAddress((void**)&wlo,  g_wlo);
    cudaGetSymbolAddress((void**)&tsin, g_sin);
    cudaGetSymbolAddress((void**)&tcos, g_cos);
    cudaGetSymbolAddress((void**)&tscl, g_scl);
    cudaGetSymbolAddress((void**)&lg2,  g_lg2);

    cudaFuncSetAttribute(k_gemm_s, cudaFuncAttributeMaxDynamicSharedMemorySize, GK_SMEM);
    cudaFuncSetAttribute(k_attn_mma, cudaFuncAttributeMaxDynamicSharedMemorySize, AT_SMEM);

    k_tables<<<32, 256>>>(tsin, tcos, tscl, lg2);   // tables needed by QKV epilogue
    k_embed_ln<<<Mn / 8, 256>>>(x, t, emb_W, emb_b, X, Xnh, Xnl, ln1_w, ln1_b);
    k_prepw_all<<<dim3(2048, 9, 4), 256>>>(WQ, WK, WV, WG, WO, f1_W, f2_W, h1_W, h2_W,
                                           whi, wlo);

    for (int l = 0; l < Ln; l++) {
        size_t lw = (size_t)l * LSW;
        if (l > 0)
            k_ln<<<Mn / 8, 256>>>(X, Xnh, Xnl, ln1_w + l * Dn, ln1_b + l * Dn);
        // fused QKV projection + xPos rotation + bf16 split (bias=tsin, wptr=tcos, extra=tscl)
        k_gemm_s<<<dim3(16, 512), 256, GK_SMEM>>>(Xnh, Xnl, whi + lw + OFF_WQ, wlo + lw + OFF_WQ,
                                                  nullptr, QKVh, QKVl, Mn, 2048, 512,
                                                  tsin, tscl, tcos, 0, EPI_ROPE_SPLIT);
        k_attn_mma<<<dim3(4, Bn * Hn), 256, AT_SMEM>>>(QKVh, QKVl, Y, lg2);
        // WG GEMM with fused GroupNorm on Y (extra): bias=gn_w, wptr=gn_b
        k_gemm_s<<<dim3(8, 512), 256, GK_SMEM>>>(Xnh, Xnl, whi + lw + OFF_WG, wlo + lw + OFF_WG,
                                                 nullptr, GYh, GYl, Mn, 1024, 512,
                                                 gn_w + l * Vn, Y, gn_b + l * Vn, 0, EPI_GN_SILU_MUL);
        k_gemm_s<<<dim3(4, 512), 256, GK_SMEM>>>(GYh, GYl, whi + lw + OFF_WO, wlo + lw + OFF_WO,
                                                 Yr, nullptr, nullptr, Mn, 512, 1024,
                                                 nullptr, X, nullptr, 0, EPI_ADD_RES);
        k_ln<<<Mn / 8, 256>>>(Yr, Xnh, Xnl, ln2_w + l * Dn, ln2_b + l * Dn);
        k_gemm_s<<<dim3(1, 512), 256, GK_SMEM>>>(Xnh, Xnl, whi + lw + OFF_F1, wlo + lw + OFF_F1,
                                                 nullptr, F1h, F1l, Mn, 128, 512,
                                                 f1_b + l * FFNn, nullptr, nullptr, 0, EPI_BIAS_GELU);
        // last layer: also emit bf16 hi/lo of X for the head
        k_gemm_s<<<dim3(4, 512), 256, GK_SMEM>>>(F1h, F1l, whi + lw + OFF_F2, wlo + lw + OFF_F2,
                                                 X, (l == Ln - 1) ? GYh : nullptr,
                                                 (l == Ln - 1) ? GYl : nullptr, Mn, 512, 128,
                                                 f2_b + l * Dn, Yr, nullptr, 0, EPI_BIAS_ADD_RES);
    }

    // head
    k_gemm_s<<<dim3(4, 512), 256, GK_SMEM>>>(GYh, GYl, whi + OFF_H1, wlo + OFF_H1,
                                             nullptr, Xnh, Xnl, Mn, 512, 512,
                                             h1_b, nullptr, wave_w, 0, EPI_BIAS_WAVE);
    k_gemm_s<<<dim3(4, 512), 256, GK_SMEM>>>(Xnh, Xnl, whi + OFF_H2, wlo + OFF_H2,
                                             Y, nullptr, nullptr, Mn, 512, 512,
                                             h2_b, nullptr, wave_w, 2, EPI_BIAS_WAVE);
    k_out<<<Mn / 8, 256>>>(Y, h3_W, h3_b, out);
}